// round 7
// baseline (speedup 1.0000x reference)
#include <cuda_runtime.h>
#include <cuda_fp16.h>
#include <cstdint>

#define HW_N1 250000
#define HW_N2 300000
#define IMG_H 1408
#define IMG_W 1408

#define MT 64
#define NCTA ((HW_N1 + MT - 1) / MT)   // 3907

#define ASTRIDE 520     // halves per A row (512 + 8 pad)
#define NSTAGE 3

// SMEM byte offsets
#define OFF_A   0u
#define OFF_W   66560u              // 64*520*2
#define WBUF_SZ 16384u              // 256 rows * 64 B (packed, swizzled)
#define OFF_IDX (OFF_W + NSTAGE * WBUF_SZ)     // 115712
#define SMEM_TOTAL (OFF_IDX + 512u)            // 116224  (2 CTAs = 227 KB)

// ---------------- device globals (sanctioned scratch) ----------------
__device__ int    g_table[4 * IMG_H * IMG_W];
__device__ __half g_W16[256 * 1024];   // W1^T(256x512) | W2^T(256x256) | W3^T(256x256)
#define W1T_OFF 0
#define W2T_OFF (256 * 512)
#define W3T_OFF (256 * 512 + 256 * 256)

// ---------------- helpers ----------------
__device__ __forceinline__ uint32_t smem_u32(const void* p) {
    uint32_t a;
    asm("{ .reg .u64 t; cvta.to.shared.u64 t, %1; cvt.u32.u64 %0, t; }"
        : "=r"(a) : "l"(p));
    return a;
}
__device__ __forceinline__ void ldmatrix_x4(uint32_t* r, uint32_t addr) {
    asm volatile("ldmatrix.sync.aligned.m8n8.x4.shared.b16 {%0,%1,%2,%3}, [%4];"
                 : "=r"(r[0]), "=r"(r[1]), "=r"(r[2]), "=r"(r[3]) : "r"(addr));
}
__device__ __forceinline__ void mma16816(float* c, const uint32_t* a,
                                         uint32_t b0, uint32_t b1) {
    asm volatile(
        "mma.sync.aligned.m16n8k16.row.col.f32.f16.f16.f32 "
        "{%0,%1,%2,%3},{%4,%5,%6,%7},{%8,%9},{%0,%1,%2,%3};"
        : "+f"(c[0]), "+f"(c[1]), "+f"(c[2]), "+f"(c[3])
        : "r"(a[0]), "r"(a[1]), "r"(a[2]), "r"(a[3]), "r"(b0), "r"(b1));
}
__device__ __forceinline__ void cpasync16(uint32_t s, const void* g) {
    asm volatile("cp.async.cg.shared.global [%0], [%1], 16;" :: "r"(s), "l"(g));
}
#define CP_COMMIT() asm volatile("cp.async.commit_group;" ::: "memory")

// W chunk layout: 256 rows x 32 halves (64 B/row), 16B-segment swizzle.
// physical byte offset of (row n, k-half group s in 0..3):
__device__ __forceinline__ uint32_t wOff(int n, int s) {
    return (uint32_t)(n * 64 + ((s ^ (n & 3)) * 16));
}

// ---------------- merged prologue kernel ----------------
__global__ void prologue_kernel(const int* __restrict__ coords2,
                                const float* __restrict__ W1,
                                const float* __restrict__ W2,
                                const float* __restrict__ W3) {
    int t = blockIdx.x * blockDim.x + threadIdx.x;
    if (t < HW_N2) {
        int b = coords2[3 * t + 0];
        int y = coords2[3 * t + 1];
        int x = coords2[3 * t + 2];
        g_table[b * (IMG_H * IMG_W) + y * IMG_W + x] = t;
    }
    if (t < 256 * 512) {
        int k = t >> 8, n = t & 255;
        g_W16[W1T_OFF + n * 512 + k] = __float2half_rn(W1[k * 256 + n]);
    }
    if (t < 256 * 256) {
        int k = t >> 8, n = t & 255;
        g_W16[W2T_OFF + n * 256 + k] = __float2half_rn(W2[k * 256 + n]);
        g_W16[W3T_OFF + n * 256 + k] = __float2half_rn(W3[k * 256 + n]);
    }
}

// ---------------- main fused kernel ----------------
__global__ void __launch_bounds__(256, 2)
fused_mma_kernel(const float* __restrict__ feat1,
                 const float* __restrict__ feat2,
                 const int*   __restrict__ coords1,
                 float*       __restrict__ out)
{
    extern __shared__ char smem[];
    const uint32_t sb = smem_u32(smem);
    __half* sA   = (__half*)(smem + OFF_A);
    int*    sIdx = (int*)(smem + OFF_IDX);

    const int tid  = threadIdx.x;
    const int lane = tid & 31;
    const int wid  = tid >> 5;
    const int wm   = wid & 1;          // 0..1  (32 rows each)
    const int wn   = wid >> 1;         // 0..3  (64 cols each)
    const int row0 = blockIdx.x * MT;

    // join indices
    if (tid < MT) {
        int gr = min(row0 + tid, HW_N1 - 1);
        int b = coords1[3 * gr + 0];
        int y = coords1[3 * gr + 1];
        int x = coords1[3 * gr + 2];
        sIdx[tid] = g_table[b * (IMG_H * IMG_W) + y * IMG_W + x];
    }
    __syncthreads();

    // ---- load A = [mf1 | mf2] as fp16 into SMEM ----
    #pragma unroll
    for (int i = 0; i < 16; ++i) {
        int e  = tid + i * 256;
        int r  = e >> 6;
        int c4 = e & 63;
        int gr = min(row0 + r, HW_N1 - 1);
        float4 v = *(const float4*)(feat1 + (size_t)gr * 256 + c4 * 4);
        __half2 h0 = __floats2half2_rn(v.x, v.y);
        __half2 h1 = __floats2half2_rn(v.z, v.w);
        uint2 u = {*(uint32_t*)&h0, *(uint32_t*)&h1};
        *(uint2*)&sA[r * ASTRIDE + c4 * 4] = u;
    }
    #pragma unroll
    for (int i = 0; i < 16; ++i) {
        int e  = tid + i * 256;
        int r  = e >> 6;
        int c4 = e & 63;
        float4 v = *(const float4*)(feat2 + (size_t)sIdx[r] * 256 + c4 * 4);
        __half2 h0 = __floats2half2_rn(v.x, v.y);
        __half2 h1 = __floats2half2_rn(v.z, v.w);
        uint2 u = {*(uint32_t*)&h0, *(uint32_t*)&h1};
        *(uint2*)&sA[r * ASTRIDE + 256 + c4 * 4] = u;
    }

    const int arow  = lane & 15;
    const int akoff = (lane >> 4) * 8;       // k-half group = lane>>4
    const int shi   = lane >> 4;             // 0 or 1

    float acc[2][8][4];

    auto zero_acc = [&]() {
        #pragma unroll
        for (int tm = 0; tm < 2; tm++)
            #pragma unroll
            for (int j = 0; j < 8; j++)
                #pragma unroll
                for (int q = 0; q < 4; q++) acc[tm][j][q] = 0.f;
    };

    // one 32-k weight chunk: 256 rows x 64B, swizzled packed layout
    auto issueW = [&](const __half* wsrc, int wKdim, int c, int buf) {
        #pragma unroll
        for (int i = 0; i < 4; ++i) {
            int l = tid + i * 256;
            int n = l >> 2;
            int s = l & 3;
            cpasync16(sb + OFF_W + (uint32_t)buf * WBUF_SZ + wOff(n, s),
                      wsrc + (size_t)n * wKdim + c * 32 + s * 8);
        }
        CP_COMMIT();
    };

    // depth-3 pipeline, one __syncthreads per chunk:
    //   iter c: wait_group<=1 (chunk c resident, c+1 may fly); sync
    //   (=> all warps done MMA(c-1)); issue c+2 into buf (c+2)%3 (last read
    //   by MMA(c-1): safe); MMA(c) on buf c%3.
    auto run_gemm = [&](const __half* wsrc, int wKdim, int nChunks, int aBase) {
        issueW(wsrc, wKdim, 0, 0);
        issueW(wsrc, wKdim, 1, 1);
        for (int c = 0; c < nChunks; ++c) {
            if (c + 1 < nChunks)
                asm volatile("cp.async.wait_group 1;" ::: "memory");
            else
                asm volatile("cp.async.wait_group 0;" ::: "memory");
            __syncthreads();
            if (c + 2 < nChunks)
                issueW(wsrc, wKdim, c + 2, (c + 2) % NSTAGE);
            const uint32_t wbase = sb + OFF_W + (uint32_t)(c % NSTAGE) * WBUF_SZ;
            #pragma unroll
            for (int ks = 0; ks < 2; ++ks) {
                const int kbA = aBase + c * 32 + ks * 16;
                uint32_t a[2][4], b[4][4];
                #pragma unroll
                for (int tm = 0; tm < 2; ++tm)
                    ldmatrix_x4(a[tm],
                        sb + ((wm * 32 + tm * 16 + arow) * ASTRIDE + kbA + akoff) * 2);
                #pragma unroll
                for (int p = 0; p < 4; ++p) {
                    int n = wn * 64 + p * 16 + arow;
                    ldmatrix_x4(b[p], wbase + wOff(n, ks * 2 + shi));
                }
                #pragma unroll
                for (int tm = 0; tm < 2; ++tm)
                    #pragma unroll
                    for (int j = 0; j < 8; ++j)
                        mma16816(acc[tm][j], a[tm], b[j >> 1][j & 1], b[j >> 1][2 + (j & 1)]);
            }
        }
        __syncthreads();   // all MMA done before caller overwrites sA
    };

    auto store_act = [&](int dstBase) {
        #pragma unroll
        for (int tm = 0; tm < 2; ++tm) {
            int r0 = wm * 32 + tm * 16 + (lane >> 2);
            #pragma unroll
            for (int j = 0; j < 8; ++j) {
                int col = wn * 64 + j * 8 + (lane & 3) * 2;
                __half2 lo = __floats2half2_rn(fmaxf(acc[tm][j][0], 0.f),
                                               fmaxf(acc[tm][j][1], 0.f));
                __half2 hi = __floats2half2_rn(fmaxf(acc[tm][j][2], 0.f),
                                               fmaxf(acc[tm][j][3], 0.f));
                *(uint32_t*)&sA[r0 * ASTRIDE + dstBase + col]       = *(uint32_t*)&lo;
                *(uint32_t*)&sA[(r0 + 8) * ASTRIDE + dstBase + col] = *(uint32_t*)&hi;
            }
        }
    };

    // GEMM1: f1 = relu([mf1|mf2] @ W1), K=512
    // (A-tile stores above are ordered by run_gemm's first in-loop sync.)
    zero_acc();
    run_gemm(g_W16 + W1T_OFF, 512, 16, 0);
    store_act(0);                      // f1 -> A cols [0,256)

    // GEMM2: f2 = relu(f1 @ W2), K=256
    zero_acc();
    run_gemm(g_W16 + W2T_OFF, 256, 8, 0);
    store_act(256);                    // f2 -> A cols [256,512)

    // GEMM3: f3 = f2 @ W3, K=256 (stays in registers)
    zero_acc();
    run_gemm(g_W16 + W3T_OFF, 256, 8, 256);

    // ---- epilogue: out = f1 * sigmoid(f3) + mf2 ----
    // (each warp reads back exactly the f1 block it wrote — no cross-warp dep)
    #pragma unroll
    for (int tm = 0; tm < 2; ++tm) {
        #pragma unroll
        for (int hh = 0; hh < 2; ++hh) {
            int rl   = wm * 32 + tm * 16 + (lane >> 2) + hh * 8;
            int grow = row0 + rl;
            if (grow < HW_N1) {
                const float* mrow = feat2 + (size_t)sIdx[rl] * 256;
                float* orow = out + (size_t)grow * 256;
                #pragma unroll
                for (int j = 0; j < 8; ++j) {
                    int col = wn * 64 + j * 8 + (lane & 3) * 2;
                    float x0 = acc[tm][j][hh * 2 + 0];
                    float x1 = acc[tm][j][hh * 2 + 1];
                    float a0 = 1.f / (1.f + __expf(-x0));
                    float a1 = 1.f / (1.f + __expf(-x1));
                    uint32_t f1u = *(uint32_t*)&sA[rl * ASTRIDE + col];
                    __half2 f1h = *(__half2*)&f1u;
                    float2 m = *(const float2*)(mrow + col);
                    float2 o;
                    o.x = __low2float(f1h)  * a0 + m.x;
                    o.y = __high2float(f1h) * a1 + m.y;
                    *(float2*)(orow + col) = o;
                }
            }
        }
    }
}

// ---------------- launch ----------------
extern "C" void kernel_launch(void* const* d_in, const int* in_sizes, int n_in,
                              void* d_out, int out_size) {
    const float* feat1   = (const float*)d_in[0];
    const float* feat2   = (const float*)d_in[1];
    const int*   coords1 = (const int*)d_in[2];
    const int*   coords2 = (const int*)d_in[3];
    const float* W1      = (const float*)d_in[4];
    const float* W2      = (const float*)d_in[5];
    const float* W3      = (const float*)d_in[6];
    float* out = (float*)d_out;

    prologue_kernel<<<(HW_N2 + 255) / 256, 256>>>(coords2, W1, W2, W3);

    cudaFuncSetAttribute(fused_mma_kernel,
                         cudaFuncAttributeMaxDynamicSharedMemorySize, SMEM_TOTAL);
    fused_mma_kernel<<<NCTA, 256, SMEM_TOTAL>>>(feat1, feat2, coords1, out);
}

// round 8
// speedup vs baseline: 1.5475x; 1.5475x over previous
#include <cuda_runtime.h>
#include <cuda_fp16.h>
#include <cstdint>

#define HW_N1 250000
#define HW_N2 300000
#define IMG_H 1408
#define IMG_W 1408

#define MT 64
#define NCTA ((HW_N1 + MT - 1) / MT)   // 3907
#define NSTAGE 3

// SMEM byte offsets
#define OFF_A   0u
#define ABUF_SZ 65536u              // 64 rows * 1024 B (packed, swizzled)
#define OFF_W   65536u
#define WBUF_SZ 16384u              // 256 rows * 64 B (packed, swizzled)
#define OFF_IDX (OFF_W + NSTAGE * WBUF_SZ)     // 114688
#define SMEM_TOTAL (OFF_IDX + 512u)            // 115200 -> 2 CTA/SM

// ---------------- device globals (sanctioned scratch) ----------------
__device__ int    g_table[4 * IMG_H * IMG_W];
__device__ __half g_W16[256 * 1024];   // W1^T(256x512) | W2^T(256x256) | W3^T(256x256)
#define W1T_OFF 0
#define W2T_OFF (256 * 512)
#define W3T_OFF (256 * 512 + 256 * 256)

// ---------------- helpers ----------------
__device__ __forceinline__ uint32_t smem_u32(const void* p) {
    uint32_t a;
    asm("{ .reg .u64 t; cvta.to.shared.u64 t, %1; cvt.u32.u64 %0, t; }"
        : "=r"(a) : "l"(p));
    return a;
}
__device__ __forceinline__ void ldmatrix_x4(uint32_t* r, uint32_t addr) {
    asm volatile("ldmatrix.sync.aligned.m8n8.x4.shared.b16 {%0,%1,%2,%3}, [%4];"
                 : "=r"(r[0]), "=r"(r[1]), "=r"(r[2]), "=r"(r[3]) : "r"(addr));
}
__device__ __forceinline__ void mma16816(float* c, const uint32_t* a,
                                         uint32_t b0, uint32_t b1) {
    asm volatile(
        "mma.sync.aligned.m16n8k16.row.col.f32.f16.f16.f32 "
        "{%0,%1,%2,%3},{%4,%5,%6,%7},{%8,%9},{%0,%1,%2,%3};"
        : "+f"(c[0]), "+f"(c[1]), "+f"(c[2]), "+f"(c[3])
        : "r"(a[0]), "r"(a[1]), "r"(a[2]), "r"(a[3]), "r"(b0), "r"(b1));
}
__device__ __forceinline__ void cpasync16(uint32_t s, const void* g) {
    asm volatile("cp.async.cg.shared.global [%0], [%1], 16;" :: "r"(s), "l"(g));
}
#define CP_COMMIT() asm volatile("cp.async.commit_group;" ::: "memory")

// W chunk layout: 256 rows x 32 halves (64 B/row), 16B-segment swizzle.
__device__ __forceinline__ uint32_t wOff(int n, int s) {
    return (uint32_t)(n * 64 + ((s ^ (n & 3)) * 16));
}
// A tile layout: 64 rows x 512 halves (1024 B/row), 16B-segment swizzle.
// halfcol must be 4-half (8B) aligned at minimum.
__device__ __forceinline__ uint32_t aOff(int r, int halfcol) {
    uint32_t byte  = (uint32_t)halfcol * 2;
    uint32_t seg   = byte >> 4;
    uint32_t inner = byte & 15;
    return ((uint32_t)r << 10) + (((seg ^ ((uint32_t)r & 7)) << 4) | inner);
}

// ---------------- merged prologue kernel ----------------
__global__ void prologue_kernel(const int* __restrict__ coords2,
                                const float* __restrict__ W1,
                                const float* __restrict__ W2,
                                const float* __restrict__ W3) {
    int t = blockIdx.x * blockDim.x + threadIdx.x;
    if (t < HW_N2) {
        int b = coords2[3 * t + 0];
        int y = coords2[3 * t + 1];
        int x = coords2[3 * t + 2];
        g_table[b * (IMG_H * IMG_W) + y * IMG_W + x] = t;
    }
    if (t < 256 * 512) {
        int k = t >> 8, n = t & 255;
        g_W16[W1T_OFF + n * 512 + k] = __float2half_rn(W1[k * 256 + n]);
    }
    if (t < 256 * 256) {
        int k = t >> 8, n = t & 255;
        g_W16[W2T_OFF + n * 256 + k] = __float2half_rn(W2[k * 256 + n]);
        g_W16[W3T_OFF + n * 256 + k] = __float2half_rn(W3[k * 256 + n]);
    }
}

// ---------------- main fused kernel ----------------
__global__ void __launch_bounds__(256, 2)
fused_mma_kernel(const float* __restrict__ feat1,
                 const float* __restrict__ feat2,
                 const int*   __restrict__ coords1,
                 float*       __restrict__ out)
{
    extern __shared__ char smem[];
    const uint32_t sb = smem_u32(smem);
    int* sIdx = (int*)(smem + OFF_IDX);

    const int tid  = threadIdx.x;
    const int lane = tid & 31;
    const int wid  = tid >> 5;
    const int wm   = wid & 1;          // 0..1  (32 rows each)
    const int wn   = wid >> 1;         // 0..3  (64 cols each)
    const int row0 = blockIdx.x * MT;

    // join indices
    if (tid < MT) {
        int gr = min(row0 + tid, HW_N1 - 1);
        int b = coords1[3 * gr + 0];
        int y = coords1[3 * gr + 1];
        int x = coords1[3 * gr + 2];
        sIdx[tid] = g_table[b * (IMG_H * IMG_W) + y * IMG_W + x];
    }
    __syncthreads();

    // ---- load A = [mf1 | mf2] as fp16 into swizzled SMEM ----
    #pragma unroll
    for (int i = 0; i < 16; ++i) {
        int e  = tid + i * 256;
        int r  = e >> 6;
        int c4 = e & 63;
        int gr = min(row0 + r, HW_N1 - 1);
        float4 v = *(const float4*)(feat1 + (size_t)gr * 256 + c4 * 4);
        __half2 h0 = __floats2half2_rn(v.x, v.y);
        __half2 h1 = __floats2half2_rn(v.z, v.w);
        uint2 u = {*(uint32_t*)&h0, *(uint32_t*)&h1};
        *(uint2*)(smem + OFF_A + aOff(r, c4 * 4)) = u;
    }
    #pragma unroll
    for (int i = 0; i < 16; ++i) {
        int e  = tid + i * 256;
        int r  = e >> 6;
        int c4 = e & 63;
        float4 v = *(const float4*)(feat2 + (size_t)sIdx[r] * 256 + c4 * 4);
        __half2 h0 = __floats2half2_rn(v.x, v.y);
        __half2 h1 = __floats2half2_rn(v.z, v.w);
        uint2 u = {*(uint32_t*)&h0, *(uint32_t*)&h1};
        *(uint2*)(smem + OFF_A + aOff(r, 256 + c4 * 4)) = u;
    }

    const int arow  = lane & 15;
    const int akoff = (lane >> 4) * 8;       // 0 or 8 halves (16B)
    const int shi   = lane >> 4;             // 0 or 1

    float acc[2][8][4];

    auto zero_acc = [&]() {
        #pragma unroll
        for (int tm = 0; tm < 2; tm++)
            #pragma unroll
            for (int j = 0; j < 8; j++)
                #pragma unroll
                for (int q = 0; q < 4; q++) acc[tm][j][q] = 0.f;
    };

    auto issueW = [&](const __half* wsrc, int wKdim, int c, int buf) {
        #pragma unroll
        for (int i = 0; i < 4; ++i) {
            int l = tid + i * 256;
            int n = l >> 2;
            int s = l & 3;
            cpasync16(sb + OFF_W + (uint32_t)buf * WBUF_SZ + wOff(n, s),
                      wsrc + (size_t)n * wKdim + c * 32 + s * 8);
        }
        CP_COMMIT();
    };

    // depth-3 pipeline, one __syncthreads per chunk:
    //   iter c: wait_group<=1 (chunk c resident, c+1 may fly); sync
    //   (all warps past MMA(c-1)); issue c+2 into buf (c+2)%3 (last read by
    //   MMA(c-1): safe); MMA(c) on buf c%3.
    auto run_gemm = [&](const __half* wsrc, int wKdim, int nChunks, int aBase) {
        issueW(wsrc, wKdim, 0, 0);
        issueW(wsrc, wKdim, 1, 1);
        for (int c = 0; c < nChunks; ++c) {
            if (c + 1 < nChunks)
                asm volatile("cp.async.wait_group 1;" ::: "memory");
            else
                asm volatile("cp.async.wait_group 0;" ::: "memory");
            __syncthreads();
            if (c + 2 < nChunks)
                issueW(wsrc, wKdim, c + 2, (c + 2) % NSTAGE);
            const uint32_t wbase = sb + OFF_W + (uint32_t)(c % NSTAGE) * WBUF_SZ;
            #pragma unroll
            for (int ks = 0; ks < 2; ++ks) {
                const int kbA = aBase + c * 32 + ks * 16;
                uint32_t a[2][4], b[4][4];
                #pragma unroll
                for (int tm = 0; tm < 2; ++tm)
                    ldmatrix_x4(a[tm],
                        sb + OFF_A + aOff(wm * 32 + tm * 16 + arow, kbA + akoff));
                #pragma unroll
                for (int p = 0; p < 4; ++p) {
                    int n = wn * 64 + p * 16 + arow;
                    ldmatrix_x4(b[p], wbase + wOff(n, ks * 2 + shi));
                }
                #pragma unroll
                for (int tm = 0; tm < 2; ++tm)
                    #pragma unroll
                    for (int j = 0; j < 8; ++j)
                        mma16816(acc[tm][j], a[tm], b[j >> 1][j & 1], b[j >> 1][2 + (j & 1)]);
            }
        }
        __syncthreads();   // all MMA done before caller overwrites A tile
    };

    auto store_act = [&](int dstBase) {
        #pragma unroll
        for (int tm = 0; tm < 2; ++tm) {
            int r0 = wm * 32 + tm * 16 + (lane >> 2);
            #pragma unroll
            for (int j = 0; j < 8; ++j) {
                int col = wn * 64 + j * 8 + (lane & 3) * 2;
                __half2 lo = __floats2half2_rn(fmaxf(acc[tm][j][0], 0.f),
                                               fmaxf(acc[tm][j][1], 0.f));
                __half2 hi = __floats2half2_rn(fmaxf(acc[tm][j][2], 0.f),
                                               fmaxf(acc[tm][j][3], 0.f));
                *(uint32_t*)(smem + OFF_A + aOff(r0,     dstBase + col)) = *(uint32_t*)&lo;
                *(uint32_t*)(smem + OFF_A + aOff(r0 + 8, dstBase + col)) = *(uint32_t*)&hi;
            }
        }
    };

    // GEMM1: f1 = relu([mf1|mf2] @ W1), K=512
    // (A-tile stores above are ordered by run_gemm's first in-loop sync.)
    zero_acc();
    run_gemm(g_W16 + W1T_OFF, 512, 16, 0);
    store_act(0);                      // f1 -> A cols [0,256)

    // GEMM2: f2 = relu(f1 @ W2), K=256
    zero_acc();
    run_gemm(g_W16 + W2T_OFF, 256, 8, 0);
    store_act(256);                    // f2 -> A cols [256,512)

    // GEMM3: f3 = f2 @ W3, K=256 (stays in registers)
    zero_acc();
    run_gemm(g_W16 + W3T_OFF, 256, 8, 256);

    // ---- epilogue: out = f1 * sigmoid(f3) + mf2 ----
    // (each warp reads back exactly the f1 block it wrote)
    #pragma unroll
    for (int tm = 0; tm < 2; ++tm) {
        #pragma unroll
        for (int hh = 0; hh < 2; ++hh) {
            int rl   = wm * 32 + tm * 16 + (lane >> 2) + hh * 8;
            int grow = row0 + rl;
            if (grow < HW_N1) {
                const float* mrow = feat2 + (size_t)sIdx[rl] * 256;
                float* orow = out + (size_t)grow * 256;
                #pragma unroll
                for (int j = 0; j < 8; ++j) {
                    int col = wn * 64 + j * 8 + (lane & 3) * 2;
                    float x0 = acc[tm][j][hh * 2 + 0];
                    float x1 = acc[tm][j][hh * 2 + 1];
                    float a0 = 1.f / (1.f + __expf(-x0));
                    float a1 = 1.f / (1.f + __expf(-x1));
                    uint32_t f1u = *(uint32_t*)(smem + OFF_A + aOff(rl, col));
                    __half2 f1h = *(__half2*)&f1u;
                    float2 m = *(const float2*)(mrow + col);
                    float2 o;
                    o.x = __low2float(f1h)  * a0 + m.x;
                    o.y = __high2float(f1h) * a1 + m.y;
                    *(float2*)(orow + col) = o;
                }
            }
        }
    }
}

// ---------------- launch ----------------
extern "C" void kernel_launch(void* const* d_in, const int* in_sizes, int n_in,
                              void* d_out, int out_size) {
    const float* feat1   = (const float*)d_in[0];
    const float* feat2   = (const float*)d_in[1];
    const int*   coords1 = (const int*)d_in[2];
    const int*   coords2 = (const int*)d_in[3];
    const float* W1      = (const float*)d_in[4];
    const float* W2      = (const float*)d_in[5];
    const float* W3      = (const float*)d_in[6];
    float* out = (float*)d_out;

    prologue_kernel<<<(HW_N2 + 255) / 256, 256>>>(coords2, W1, W2, W3);

    cudaFuncSetAttribute(fused_mma_kernel,
                         cudaFuncAttributeMaxDynamicSharedMemorySize, SMEM_TOTAL);
    fused_mma_kernel<<<NCTA, 256, SMEM_TOTAL>>>(feat1, feat2, coords1, out);
}

// round 9
// speedup vs baseline: 1.8633x; 1.2041x over previous
#include <cuda_runtime.h>
#include <cuda_fp16.h>
#include <cstdint>

#define HW_N1 250000
#define HW_N2 300000
#define IMG_H 1408
#define IMG_W 1408

#define MT 64
#define NCTA ((HW_N1 + MT - 1) / MT)   // 3907

// SMEM: A tile (64 x 512 halves, packed 1024 B/row, swizzled) + idx
#define OFF_A   0u
#define OFF_IDX 65536u
#define SMEM_TOTAL 66048u

// ---------------- device globals (sanctioned scratch) ----------------
__device__ int g_table[4 * IMG_H * IMG_W];
// B fragments in mma m16n8k16 register order:
// slot = ((s * 16 + t) * 32 + lane), each slot = uint4 (4 x u32 = 8 halves)
//   s = k16 step, t = n16 tile (N=256 -> 16 tiles), lane = 0..31
//   .x = b0 of n8-tile0, .y = b0 of n8-tile1, .z = b1 tile0, .w = b1 tile1
__device__ uint32_t g_Wfrag[128 * 1024];   // 512 KB total
#define WF1_OFF 0
#define WF2_OFF 65536
#define WF3_OFF 98304
#define WF1_SLOTS (32 * 16 * 32)   // 16384
#define WF23_SLOTS (16 * 16 * 32)  // 8192

// ---------------- helpers ----------------
__device__ __forceinline__ uint32_t smem_u32(const void* p) {
    uint32_t a;
    asm("{ .reg .u64 t; cvta.to.shared.u64 t, %1; cvt.u32.u64 %0, t; }"
        : "=r"(a) : "l"(p));
    return a;
}
__device__ __forceinline__ void ldmatrix_x4(uint32_t* r, uint32_t addr) {
    asm volatile("ldmatrix.sync.aligned.m8n8.x4.shared.b16 {%0,%1,%2,%3}, [%4];"
                 : "=r"(r[0]), "=r"(r[1]), "=r"(r[2]), "=r"(r[3]) : "r"(addr));
}
__device__ __forceinline__ void mma16816(float* c, const uint32_t* a,
                                         uint32_t b0, uint32_t b1) {
    asm volatile(
        "mma.sync.aligned.m16n8k16.row.col.f32.f16.f16.f32 "
        "{%0,%1,%2,%3},{%4,%5,%6,%7},{%8,%9},{%0,%1,%2,%3};"
        : "+f"(c[0]), "+f"(c[1]), "+f"(c[2]), "+f"(c[3])
        : "r"(a[0]), "r"(a[1]), "r"(a[2]), "r"(a[3]), "r"(b0), "r"(b1));
}
// A tile layout: 64 rows x 512 halves (1024 B/row), 16B-segment swizzle.
__device__ __forceinline__ uint32_t aOff(int r, int halfcol) {
    uint32_t byte  = (uint32_t)halfcol * 2;
    uint32_t seg   = byte >> 4;
    uint32_t inner = byte & 15;
    return ((uint32_t)r << 10) + (((seg ^ ((uint32_t)r & 7)) << 4) | inner);
}
__device__ __forceinline__ uint32_t packh2(float lo, float hi) {
    __half2 h = __floats2half2_rn(lo, hi);
    return *(uint32_t*)&h;
}

// ---------------- prologue: table + fragment-order weights ----------------
__device__ __forceinline__ void write_frag(const float* __restrict__ W,
                                           uint32_t* __restrict__ dst, int slot) {
    int lane = slot & 31;
    int st   = slot >> 5;
    int t    = st & 15;
    int s    = st >> 4;
    int kk   = s * 16 + (lane & 3) * 2;    // even k within step
    int n0   = t * 16 + (lane >> 2);
    int n1   = n0 + 8;
    uint4 v;
    v.x = packh2(W[kk * 256 + n0],       W[(kk + 1) * 256 + n0]);
    v.y = packh2(W[kk * 256 + n1],       W[(kk + 1) * 256 + n1]);
    v.z = packh2(W[(kk + 8) * 256 + n0], W[(kk + 9) * 256 + n0]);
    v.w = packh2(W[(kk + 8) * 256 + n1], W[(kk + 9) * 256 + n1]);
    ((uint4*)dst)[slot] = v;
}

__global__ void prologue_kernel(const int* __restrict__ coords2,
                                const float* __restrict__ W1,
                                const float* __restrict__ W2,
                                const float* __restrict__ W3) {
    int t = blockIdx.x * blockDim.x + threadIdx.x;
    if (t < HW_N2) {
        int b = coords2[3 * t + 0];
        int y = coords2[3 * t + 1];
        int x = coords2[3 * t + 2];
        g_table[b * (IMG_H * IMG_W) + y * IMG_W + x] = t;
    }
    if (t < WF1_SLOTS)
        write_frag(W1, g_Wfrag + WF1_OFF, t);
    if (t < WF23_SLOTS) {
        write_frag(W2, g_Wfrag + WF2_OFF, t);
        write_frag(W3, g_Wfrag + WF3_OFF, t);
    }
}

// ---------------- main fused kernel ----------------
__global__ void __launch_bounds__(256, 2)
fused_mma_kernel(const float* __restrict__ feat1,
                 const float* __restrict__ feat2,
                 const int*   __restrict__ coords1,
                 float*       __restrict__ out)
{
    extern __shared__ char smem[];
    const uint32_t sb = smem_u32(smem);
    int* sIdx = (int*)(smem + OFF_IDX);

    const int tid  = threadIdx.x;
    const int lane = tid & 31;
    const int wid  = tid >> 5;
    const int wm   = wid & 1;          // 0..1  (32 rows each)
    const int wn   = wid >> 1;         // 0..3  (64 cols each)
    const int row0 = blockIdx.x * MT;

    // join indices
    if (tid < MT) {
        int gr = min(row0 + tid, HW_N1 - 1);
        int b = coords1[3 * gr + 0];
        int y = coords1[3 * gr + 1];
        int x = coords1[3 * gr + 2];
        sIdx[tid] = g_table[b * (IMG_H * IMG_W) + y * IMG_W + x];
    }
    __syncthreads();

    // ---- load A = [mf1 | mf2] as fp16 into swizzled SMEM ----
    #pragma unroll
    for (int i = 0; i < 16; ++i) {
        int e  = tid + i * 256;
        int r  = e >> 6;
        int c4 = e & 63;
        int gr = min(row0 + r, HW_N1 - 1);
        float4 v = *(const float4*)(feat1 + (size_t)gr * 256 + c4 * 4);
        uint2 u = {packh2(v.x, v.y), packh2(v.z, v.w)};
        *(uint2*)(smem + OFF_A + aOff(r, c4 * 4)) = u;
    }
    #pragma unroll
    for (int i = 0; i < 16; ++i) {
        int e  = tid + i * 256;
        int r  = e >> 6;
        int c4 = e & 63;
        float4 v = *(const float4*)(feat2 + (size_t)sIdx[r] * 256 + c4 * 4);
        uint2 u = {packh2(v.x, v.y), packh2(v.z, v.w)};
        *(uint2*)(smem + OFF_A + aOff(r, 256 + c4 * 4)) = u;
    }
    __syncthreads();   // A tile visible to all warps before GEMM1

    const int arow  = lane & 15;
    const int akoff = (lane >> 4) * 8;       // 0 or 8 halves (16B)

    float acc[2][8][4];

    auto zero_acc = [&]() {
        #pragma unroll
        for (int tm = 0; tm < 2; tm++)
            #pragma unroll
            for (int j = 0; j < 8; j++)
                #pragma unroll
                for (int q = 0; q < 4; q++) acc[tm][j][q] = 0.f;
    };

    // B-from-global GEMM: no smem staging, no barriers in the k-loop.
    // Double-buffered B fragments in registers (4 x uint4 per step).
    auto run_gemm = [&](const uint32_t* __restrict__ wfrag, int nK16, int aBase) {
        const uint4* __restrict__ wf = (const uint4*)wfrag;
        const int tbase = wn * 4;             // this warp's first n16 tile
        uint4 Bb[2][4];
        #pragma unroll
        for (int p = 0; p < 4; ++p)
            Bb[0][p] = __ldg(wf + (size_t)((0 * 16 + tbase + p) * 32 + lane));
        #pragma unroll 2
        for (int s = 0; s < nK16; ++s) {
            const int cur = s & 1;
            if (s + 1 < nK16) {
                #pragma unroll
                for (int p = 0; p < 4; ++p)
                    Bb[cur ^ 1][p] =
                        __ldg(wf + (size_t)(((s + 1) * 16 + tbase + p) * 32 + lane));
            }
            uint32_t a[2][4];
            #pragma unroll
            for (int tm = 0; tm < 2; ++tm)
                ldmatrix_x4(a[tm],
                    sb + OFF_A + aOff(wm * 32 + tm * 16 + arow,
                                      aBase + s * 16 + akoff));
            #pragma unroll
            for (int tm = 0; tm < 2; ++tm)
                #pragma unroll
                for (int j = 0; j < 8; ++j) {
                    const uint4& f = Bb[cur][j >> 1];
                    uint32_t b0 = (j & 1) ? f.y : f.x;
                    uint32_t b1 = (j & 1) ? f.w : f.z;
                    mma16816(acc[tm][j], a[tm], b0, b1);
                }
        }
    };

    auto store_act = [&](int dstBase) {
        #pragma unroll
        for (int tm = 0; tm < 2; ++tm) {
            int r0 = wm * 32 + tm * 16 + (lane >> 2);
            #pragma unroll
            for (int j = 0; j < 8; ++j) {
                int col = wn * 64 + j * 8 + (lane & 3) * 2;
                uint32_t lo = packh2(fmaxf(acc[tm][j][0], 0.f),
                                     fmaxf(acc[tm][j][1], 0.f));
                uint32_t hi = packh2(fmaxf(acc[tm][j][2], 0.f),
                                     fmaxf(acc[tm][j][3], 0.f));
                *(uint32_t*)(smem + OFF_A + aOff(r0,     dstBase + col)) = lo;
                *(uint32_t*)(smem + OFF_A + aOff(r0 + 8, dstBase + col)) = hi;
            }
        }
    };

    // GEMM1: f1 = relu([mf1|mf2] @ W1), K=512 (32 k16 steps)
    zero_acc();
    run_gemm(g_Wfrag + WF1_OFF, 32, 0);
    __syncthreads();                   // all MMA reads of mf1 done
    store_act(0);                      // f1 -> A cols [0,256)
    __syncthreads();                   // f1 visible to all warps

    // GEMM2: f2 = relu(f1 @ W2), K=256 (16 steps)
    zero_acc();
    run_gemm(g_Wfrag + WF2_OFF, 16, 0);
    __syncthreads();                   // all MMA reads of mf2 region done
    store_act(256);                    // f2 -> A cols [256,512)
    __syncthreads();                   // f2 visible to all warps

    // GEMM3: f3 = f2 @ W3, K=256 (stays in registers)
    zero_acc();
    run_gemm(g_Wfrag + WF3_OFF, 16, 256);

    // ---- epilogue: out = f1 * sigmoid(f3) + mf2 ----
    // (each warp reads back exactly the f1 block it wrote)
    #pragma unroll
    for (int tm = 0; tm < 2; ++tm) {
        #pragma unroll
        for (int hh = 0; hh < 2; ++hh) {
            int rl   = wm * 32 + tm * 16 + (lane >> 2) + hh * 8;
            int grow = row0 + rl;
            if (grow < HW_N1) {
                const float* mrow = feat2 + (size_t)sIdx[rl] * 256;
                float* orow = out + (size_t)grow * 256;
                #pragma unroll
                for (int j = 0; j < 8; ++j) {
                    int col = wn * 64 + j * 8 + (lane & 3) * 2;
                    float x0 = acc[tm][j][hh * 2 + 0];
                    float x1 = acc[tm][j][hh * 2 + 1];
                    float a0 = 1.f / (1.f + __expf(-x0));
                    float a1 = 1.f / (1.f + __expf(-x1));
                    uint32_t f1u = *(uint32_t*)(smem + OFF_A + aOff(rl, col));
                    __half2 f1h = *(__half2*)&f1u;
                    float2 m = *(const float2*)(mrow + col);
                    float2 o;
                    o.x = __low2float(f1h)  * a0 + m.x;
                    o.y = __high2float(f1h) * a1 + m.y;
                    *(float2*)(orow + col) = o;
                }
            }
        }
    }
}

// ---------------- launch ----------------
extern "C" void kernel_launch(void* const* d_in, const int* in_sizes, int n_in,
                              void* d_out, int out_size) {
    const float* feat1   = (const float*)d_in[0];
    const float* feat2   = (const float*)d_in[1];
    const int*   coords1 = (const int*)d_in[2];
    const int*   coords2 = (const int*)d_in[3];
    const float* W1      = (const float*)d_in[4];
    const float* W2      = (const float*)d_in[5];
    const float* W3      = (const float*)d_in[6];
    float* out = (float*)d_out;

    prologue_kernel<<<(HW_N2 + 255) / 256, 256>>>(coords2, W1, W2, W3);

    cudaFuncSetAttribute(fused_mma_kernel,
                         cudaFuncAttributeMaxDynamicSharedMemorySize, SMEM_TOTAL);
    fused_mma_kernel<<<NCTA, 256, SMEM_TOTAL>>>(feat1, feat2, coords1, out);
}